// round 6
// baseline (speedup 1.0000x reference)
#include <cuda_runtime.h>
#include <cstdint>

// LJ constants (sigma = 1, epsilon = 1, cutoff = 5)
// SHIFT = 4*((1/5)^12 - (1/5)^6)
static __device__ __constant__ float c_shift = 4.0f * (float)(4.096e-09 - 6.4e-05);

// Runtime flag: 1 if index arrays are int64, 0 if int32 (device-detected).
__device__ int g_idx64;

// Fused: zero the per-atom accumulators AND detect index dtype (one node).
__global__ void zero_and_detect_kernel(float4* __restrict__ out4, int n4,
                                       float* __restrict__ out, int n,
                                       const unsigned int* __restrict__ fa) {
    int i = blockIdx.x * blockDim.x + threadIdx.x;
    // Vectorized zero of the float output buffer.
    if (i < n4) out4[i] = make_float4(0.f, 0.f, 0.f, 0.f);
    // Scalar remainder.
    int r = 4 * n4 + i;
    if (r < n) out[r] = 0.f;
    // Dtype probe: int64-LE with values < 2^31 -> odd 32-bit words all zero.
    // int32 indices in [0, 100000): odd words are real indices; all-zero
    // false-positive probability ~(1e-5)^16 -> negligible.
    if (i == 0) {
        unsigned int acc = 0;
#pragma unroll
        for (int k = 0; k < 16; k++) acc |= fa[2 * k + 1];
        g_idx64 = (acc == 0) ? 1 : 0;
    }
}

__device__ __forceinline__ float lj_half_energy(float x, float y, float z) {
    float r2 = fmaf(x, x, fmaf(y, y, z * z));
    float inv = 1.0f / r2;              // (sigma/r)^2 with sigma = 1
    float sr6 = inv * inv * inv;        // (sigma/r)^6
    float e = fmaf(4.0f, fmaf(sr6, sr6, -sr6), -c_shift);
    return 0.5f * e;
}

// Main kernel (R1 winning config): 4 edges/thread, block = 256, one-shot grid,
// uniform branch on g_idx64.
__global__ void __launch_bounds__(256) lj_kernel(
    const float4* __restrict__ d4,
    const void* __restrict__ fa,
    const void* __restrict__ sa,
    float* __restrict__ out,
    int n_quads)
{
    int i = blockIdx.x * blockDim.x + threadIdx.x;
    if (i >= n_quads) return;

    // 4 edges = 12 floats = 3 x float4, fully coalesced.
    float4 a = d4[3 * (size_t)i + 0];
    float4 b = d4[3 * (size_t)i + 1];
    float4 c = d4[3 * (size_t)i + 2];

    float h0 = lj_half_energy(a.x, a.y, a.z);
    float h1 = lj_half_energy(a.w, b.x, b.y);
    float h2 = lj_half_energy(b.z, b.w, c.x);
    float h3 = lj_half_energy(c.y, c.z, c.w);

    if (!g_idx64) {
        int4 f = ((const int4*)fa)[i];
        int4 s = ((const int4*)sa)[i];
        atomicAdd(out + f.x, h0); atomicAdd(out + s.x, h0);
        atomicAdd(out + f.y, h1); atomicAdd(out + s.y, h1);
        atomicAdd(out + f.z, h2); atomicAdd(out + s.z, h2);
        atomicAdd(out + f.w, h3); atomicAdd(out + s.w, h3);
    } else {
        longlong2 f01 = ((const longlong2*)fa)[2 * (size_t)i + 0];
        longlong2 f23 = ((const longlong2*)fa)[2 * (size_t)i + 1];
        longlong2 s01 = ((const longlong2*)sa)[2 * (size_t)i + 0];
        longlong2 s23 = ((const longlong2*)sa)[2 * (size_t)i + 1];
        atomicAdd(out + f01.x, h0); atomicAdd(out + s01.x, h0);
        atomicAdd(out + f01.y, h1); atomicAdd(out + s01.y, h1);
        atomicAdd(out + f23.x, h2); atomicAdd(out + s23.x, h2);
        atomicAdd(out + f23.y, h3); atomicAdd(out + s23.y, h3);
    }
}

// Scalar tail for n_edges not divisible by 4 (skipped at capture when rem==0).
__global__ void lj_tail_kernel(
    const float* __restrict__ dist,
    const void* __restrict__ fa,
    const void* __restrict__ sa,
    float* __restrict__ out,
    int start, int n_edges)
{
    int e = start + blockIdx.x * blockDim.x + threadIdx.x;
    if (e >= n_edges) return;
    float x = dist[3 * (size_t)e + 0];
    float y = dist[3 * (size_t)e + 1];
    float z = dist[3 * (size_t)e + 2];
    float h = lj_half_energy(x, y, z);
    long long i0, i1;
    if (g_idx64) {
        i0 = ((const long long*)fa)[e];
        i1 = ((const long long*)sa)[e];
    } else {
        i0 = ((const int*)fa)[e];
        i1 = ((const int*)sa)[e];
    }
    atomicAdd(out + i0, h);
    atomicAdd(out + i1, h);
}

extern "C" void kernel_launch(void* const* d_in, const int* in_sizes, int n_in,
                              void* d_out, int out_size)
{
    const float* dist = (const float*)d_in[0];
    const void*  fa   = d_in[1];
    const void*  sa   = d_in[2];
    float* out = (float*)d_out;

    int n_edges = in_sizes[1];  // element count of first_atom

    // Node 1: zero accumulators + detect index dtype.
    {
        int n4 = out_size / 4;
        int work = (n4 > 0) ? n4 : 1;
        int threads = 256;
        int blocks = (work + threads - 1) / threads;
        zero_and_detect_kernel<<<blocks, threads>>>(
            (float4*)d_out, n4, out, out_size, (const unsigned int*)fa);
    }

    // Node 2: main kernel.
    int quads = n_edges / 4;
    if (quads > 0) {
        int threads = 256;
        int blocks = (quads + threads - 1) / threads;
        lj_kernel<<<blocks, threads>>>((const float4*)dist, fa, sa, out, quads);
    }

    // Optional node 3: tail (only if n_edges % 4 != 0; not the case here).
    int rem_start = quads * 4;
    if (rem_start < n_edges) {
        int rem = n_edges - rem_start;
        lj_tail_kernel<<<(rem + 255) / 256, 256>>>(dist, fa, sa, out, rem_start, n_edges);
    }
}

// round 7
// speedup vs baseline: 1.1004x; 1.1004x over previous
#include <cuda_runtime.h>
#include <cstdint>

// LJ constants (sigma = 1, epsilon = 1, cutoff = 5)
// SHIFT = 4*((1/5)^12 - (1/5)^6)
static __device__ __constant__ float c_shift = 4.0f * (float)(4.096e-09 - 6.4e-05);

// Runtime flag: 1 if index arrays are int64, 0 if int32 (device-detected).
__device__ int g_idx64;

__global__ void detect_idx_dtype_kernel(const unsigned int* __restrict__ fa) {
    if (threadIdx.x == 0) {
        // int64-LE with values < 2^31 -> odd 32-bit words all zero.
        // int32 indices in [0, 100000): odd words are real indices; all-zero
        // false-positive probability ~(1e-5)^16 -> negligible.
        unsigned int acc = 0;
#pragma unroll
        for (int k = 0; k < 16; k++) acc |= fa[2 * k + 1];
        g_idx64 = (acc == 0) ? 1 : 0;
    }
}

__device__ __forceinline__ float lj_half_energy(float x, float y, float z) {
    float r2 = fmaf(x, x, fmaf(y, y, z * z));
    float inv = 1.0f / r2;              // (sigma/r)^2 with sigma = 1
    float sr6 = inv * inv * inv;        // (sigma/r)^6
    float e = fmaf(4.0f, fmaf(sr6, sr6, -sr6), -c_shift);
    return 0.5f * e;
}

// Main kernel (measured-best config across 6 variants): 4 edges per thread,
// block = 256, one-shot grid, fire-and-forget atomics (REDG), uniform branch
// on g_idx64. The kernel is pinned at the scatter-atomic wavefront floor;
// this geometry had the best measured sample and the best ncu profile
// (occ 82%, L2 71.6%).
__global__ void __launch_bounds__(256) lj_kernel(
    const float4* __restrict__ d4,
    const void* __restrict__ fa,
    const void* __restrict__ sa,
    float* __restrict__ out,
    int n_quads)
{
    int i = blockIdx.x * blockDim.x + threadIdx.x;
    if (i >= n_quads) return;

    // 4 edges = 12 floats = 3 x float4, fully coalesced.
    float4 a = d4[3 * (size_t)i + 0];
    float4 b = d4[3 * (size_t)i + 1];
    float4 c = d4[3 * (size_t)i + 2];

    float h0 = lj_half_energy(a.x, a.y, a.z);
    float h1 = lj_half_energy(a.w, b.x, b.y);
    float h2 = lj_half_energy(b.z, b.w, c.x);
    float h3 = lj_half_energy(c.y, c.z, c.w);

    if (!g_idx64) {
        int4 f = ((const int4*)fa)[i];
        int4 s = ((const int4*)sa)[i];
        atomicAdd(out + f.x, h0); atomicAdd(out + s.x, h0);
        atomicAdd(out + f.y, h1); atomicAdd(out + s.y, h1);
        atomicAdd(out + f.z, h2); atomicAdd(out + s.z, h2);
        atomicAdd(out + f.w, h3); atomicAdd(out + s.w, h3);
    } else {
        longlong2 f01 = ((const longlong2*)fa)[2 * (size_t)i + 0];
        longlong2 f23 = ((const longlong2*)fa)[2 * (size_t)i + 1];
        longlong2 s01 = ((const longlong2*)sa)[2 * (size_t)i + 0];
        longlong2 s23 = ((const longlong2*)sa)[2 * (size_t)i + 1];
        atomicAdd(out + f01.x, h0); atomicAdd(out + s01.x, h0);
        atomicAdd(out + f01.y, h1); atomicAdd(out + s01.y, h1);
        atomicAdd(out + f23.x, h2); atomicAdd(out + s23.x, h2);
        atomicAdd(out + f23.y, h3); atomicAdd(out + s23.y, h3);
    }
}

// Scalar tail for n_edges not divisible by 4 (skipped at capture when rem==0).
__global__ void lj_tail_kernel(
    const float* __restrict__ dist,
    const void* __restrict__ fa,
    const void* __restrict__ sa,
    float* __restrict__ out,
    int start, int n_edges)
{
    int e = start + blockIdx.x * blockDim.x + threadIdx.x;
    if (e >= n_edges) return;
    float x = dist[3 * (size_t)e + 0];
    float y = dist[3 * (size_t)e + 1];
    float z = dist[3 * (size_t)e + 2];
    float h = lj_half_energy(x, y, z);
    long long i0, i1;
    if (g_idx64) {
        i0 = ((const long long*)fa)[e];
        i1 = ((const long long*)sa)[e];
    } else {
        i0 = ((const int*)fa)[e];
        i1 = ((const int*)sa)[e];
    }
    atomicAdd(out + i0, h);
    atomicAdd(out + i1, h);
}

extern "C" void kernel_launch(void* const* d_in, const int* in_sizes, int n_in,
                              void* d_out, int out_size)
{
    const float* dist = (const float*)d_in[0];
    const void*  fa   = d_in[1];
    const void*  sa   = d_in[2];
    float* out = (float*)d_out;

    int n_edges = in_sizes[1];  // element count of first_atom

    // Zero per-atom accumulators (d_out is poisoned before timing).
    cudaMemsetAsync(d_out, 0, (size_t)out_size * sizeof(float));

    // Detect index dtype (1 warp; overlaps nothing meaningful, ~2 us node).
    detect_idx_dtype_kernel<<<1, 32>>>((const unsigned int*)fa);

    // Main kernel.
    int quads = n_edges / 4;
    if (quads > 0) {
        int threads = 256;
        int blocks = (quads + threads - 1) / threads;
        lj_kernel<<<blocks, threads>>>((const float4*)dist, fa, sa, out, quads);
    }

    // Tail only if n_edges % 4 != 0 (not the case for 6.4M edges).
    int rem_start = quads * 4;
    if (rem_start < n_edges) {
        int rem = n_edges - rem_start;
        lj_tail_kernel<<<(rem + 255) / 256, 256>>>(dist, fa, sa, out, rem_start, n_edges);
    }
}

// round 8
// speedup vs baseline: 1.1278x; 1.0249x over previous
#include <cuda_runtime.h>
#include <cstdint>

// LJ constants (sigma = 1, epsilon = 1, cutoff = 5)
// SHIFT = 4*((1/5)^12 - (1/5)^6)
static __device__ __constant__ float c_shift = 4.0f * (float)(4.096e-09 - 6.4e-05);

// Runtime flag: 1 if index arrays are int64, 0 if int32 (device-detected).
__device__ int g_idx64;

// Fused node 1: zero the per-atom accumulators AND detect index dtype.
__global__ void __launch_bounds__(256) zero_and_detect_kernel(
    float4* __restrict__ out4, int n4,
    float* __restrict__ out, int n,
    const unsigned int* __restrict__ fa)
{
    int i = blockIdx.x * blockDim.x + threadIdx.x;
    if (i < n4) out4[i] = make_float4(0.f, 0.f, 0.f, 0.f);
    int r = 4 * n4 + i;
    if (r < n) out[r] = 0.f;
    if (i == 0) {
        // int64-LE with values < 2^31 -> odd 32-bit words all zero.
        // int32 indices in [0, 100000): odd words are real indices; all-zero
        // false-positive probability ~(1e-5)^16 -> negligible.
        unsigned int acc = 0;
#pragma unroll
        for (int k = 0; k < 16; k++) acc |= fa[2 * k + 1];
        g_idx64 = (acc == 0) ? 1 : 0;
    }
}

__device__ __forceinline__ float lj_half_energy(float x, float y, float z) {
    float r2 = fmaf(x, x, fmaf(y, y, z * z));
    float inv = 1.0f / r2;              // (sigma/r)^2 with sigma = 1
    float sr6 = inv * inv * inv;        // (sigma/r)^6
    float e = fmaf(4.0f, fmaf(sr6, sr6, -sr6), -c_shift);
    return 0.5f * e;
}

// Main kernel — byte-identical hot loop to the measured-best config:
// 4 edges/thread, block = 256, one-shot grid, fire-and-forget REDG atomics,
// uniform branch on g_idx64. Pinned at the scatter-atomic wavefront floor.
__global__ void __launch_bounds__(256) lj_kernel(
    const float4* __restrict__ d4,
    const void* __restrict__ fa,
    const void* __restrict__ sa,
    float* __restrict__ out,
    int n_quads)
{
    int i = blockIdx.x * blockDim.x + threadIdx.x;
    if (i >= n_quads) return;

    // 4 edges = 12 floats = 3 x float4, fully coalesced.
    float4 a = d4[3 * (size_t)i + 0];
    float4 b = d4[3 * (size_t)i + 1];
    float4 c = d4[3 * (size_t)i + 2];

    float h0 = lj_half_energy(a.x, a.y, a.z);
    float h1 = lj_half_energy(a.w, b.x, b.y);
    float h2 = lj_half_energy(b.z, b.w, c.x);
    float h3 = lj_half_energy(c.y, c.z, c.w);

    if (!g_idx64) {
        int4 f = ((const int4*)fa)[i];
        int4 s = ((const int4*)sa)[i];
        atomicAdd(out + f.x, h0); atomicAdd(out + s.x, h0);
        atomicAdd(out + f.y, h1); atomicAdd(out + s.y, h1);
        atomicAdd(out + f.z, h2); atomicAdd(out + s.z, h2);
        atomicAdd(out + f.w, h3); atomicAdd(out + s.w, h3);
    } else {
        longlong2 f01 = ((const longlong2*)fa)[2 * (size_t)i + 0];
        longlong2 f23 = ((const longlong2*)fa)[2 * (size_t)i + 1];
        longlong2 s01 = ((const longlong2*)sa)[2 * (size_t)i + 0];
        longlong2 s23 = ((const longlong2*)sa)[2 * (size_t)i + 1];
        atomicAdd(out + f01.x, h0); atomicAdd(out + s01.x, h0);
        atomicAdd(out + f01.y, h1); atomicAdd(out + s01.y, h1);
        atomicAdd(out + f23.x, h2); atomicAdd(out + s23.x, h2);
        atomicAdd(out + f23.y, h3); atomicAdd(out + s23.y, h3);
    }
}

// Scalar tail for n_edges not divisible by 4 (skipped at capture when rem==0).
__global__ void lj_tail_kernel(
    const float* __restrict__ dist,
    const void* __restrict__ fa,
    const void* __restrict__ sa,
    float* __restrict__ out,
    int start, int n_edges)
{
    int e = start + blockIdx.x * blockDim.x + threadIdx.x;
    if (e >= n_edges) return;
    float x = dist[3 * (size_t)e + 0];
    float y = dist[3 * (size_t)e + 1];
    float z = dist[3 * (size_t)e + 2];
    float h = lj_half_energy(x, y, z);
    long long i0, i1;
    if (g_idx64) {
        i0 = ((const long long*)fa)[e];
        i1 = ((const long long*)sa)[e];
    } else {
        i0 = ((const int*)fa)[e];
        i1 = ((const int*)sa)[e];
    }
    atomicAdd(out + i0, h);
    atomicAdd(out + i1, h);
}

extern "C" void kernel_launch(void* const* d_in, const int* in_sizes, int n_in,
                              void* d_out, int out_size)
{
    const float* dist = (const float*)d_in[0];
    const void*  fa   = d_in[1];
    const void*  sa   = d_in[2];
    float* out = (float*)d_out;

    int n_edges = in_sizes[1];  // element count of first_atom

    // Node 1: zero accumulators + detect index dtype (replaces memset+detect).
    {
        int n4 = out_size / 4;
        int work = (n4 > 0) ? n4 : 1;
        int blocks = (work + 255) / 256;
        zero_and_detect_kernel<<<blocks, 256>>>(
            (float4*)d_out, n4, out, out_size, (const unsigned int*)fa);
    }

    // Node 2: main kernel.
    int quads = n_edges / 4;
    if (quads > 0) {
        int blocks = (quads + 255) / 256;
        lj_kernel<<<blocks, 256>>>((const float4*)dist, fa, sa, out, quads);
    }

    // Tail only if n_edges % 4 != 0 (not the case for 6.4M edges).
    int rem_start = quads * 4;
    if (rem_start < n_edges) {
        int rem = n_edges - rem_start;
        lj_tail_kernel<<<(rem + 255) / 256, 256>>>(dist, fa, sa, out, rem_start, n_edges);
    }
}